// round 14
// baseline (speedup 1.0000x reference)
#include <cuda_runtime.h>
#include <cuda_fp16.h>
#include <math.h>

#define B     40000
#define D     128
#define D4    (D/4)
#define ND    200000
#define ESUB  320000
#define ESUP  1280000
#define SLOTS 128          // max edges per output row (mean 40, 14-sigma safe)

// Prep sectioning: single full wave (<=1184 blocks @ 256thr, 8 blocks/SM).
// mod-5 interleave: B (streaming convert, ~153MB) 3/5, A and C 1/5 each.
#define PREP_GRID 1180
#define GA 236
#define GB 708
#define GC 236

// Scratch (static device globals — no allocation in kernel_launch)
// Single contiguous fp16 source matrix: rows [0, ND) = old_activation,
// rows [ND, ND+B) = diff. Fill precomputes element offsets into this array.
__device__ __half g_src_h[(size_t)(ND + B) * D];   // 61.4 MB — pinned in L2
__device__ float g_dots[3];
__device__ unsigned int g_ticket = 0;
__device__ int  g_cnt[B];                    // zero-init; accumulate re-zeros
__device__ int2 g_meta[(size_t)B * SLOTS];   // (src_elem_offset, val_bits)

// ---- L2 retention-priority store: sm_103 requires 256-bit shapes for
// .L2::evict_last (both ld and st). Only the .v8.b32 store form is used. ----
__device__ __forceinline__ void st_el_v8(void* p, const unsigned int* v) {
    asm volatile("st.global.L2::evict_last.v8.b32 [%0], {%1,%2,%3,%4,%5,%6,%7,%8};"
                 :: "l"(p), "r"(v[0]), "r"(v[1]), "r"(v[2]), "r"(v[3]),
                    "r"(v[4]), "r"(v[5]), "r"(v[6]), "r"(v[7]) : "memory");
}

// ---------------------------------------------------------------------------
// Fused prep kernel, traffic-weighted section interleave.
// Single-use streams: evict-first (__ldcs). The fp16 src working set is
// written with 256-bit evict-last stores so its lines stay resident in L2
// for the accumulate kernel.
__global__ void __launch_bounds__(256) prep_kernel(
        const float* __restrict__ inputs,
        const float* __restrict__ old_act,
        const int*   __restrict__ fields,
        const int*   __restrict__ sub_rows,
        const int*   __restrict__ sub_cols,
        const float* __restrict__ sub_vals,
        const int*   __restrict__ sup_rows,
        const int*   __restrict__ sup_cols,
        const float* __restrict__ sup_vals,
        float*       __restrict__ out,
        int out_size) {
    const int m5 = blockIdx.x % 5;

    if (m5 == 0) {
        // ---- Section A: gather old rows, diff (fp16 into g_src_h[ND..]),
        //      three dot products; last finisher writes sim.
        //      Each thread: one 16-float segment -> one 32B evict-last store.
        const int sb = blockIdx.x / 5;
        __shared__ float s_red[3][8];
        const int tid   = sb * blockDim.x + threadIdx.x;
        const int nthr  = GA * blockDim.x;
        const int total = (B * D) / 16;      // 16 floats per item

        float dot = 0.0f, nin = 0.0f, nold = 0.0f;

        const float4* in4  = (const float4*)inputs;
        const float4* old4 = (const float4*)old_act;
        __half*       df   = g_src_h + (size_t)ND * D;

        for (int i = tid; i < total; i += nthr) {
            const int row = i >> 3;          // 8 segments per 128-float row
            const int seg = i & 7;
            const int f   = __ldg(&fields[row]);
            const float4* ip = in4  + (size_t)row * 32 + seg * 4;
            const float4* op = old4 + (size_t)f   * 32 + seg * 4;

            unsigned int pk[8];
            #pragma unroll
            for (int j = 0; j < 4; j++) {
                float4 a = __ldcs(ip + j);               // single-use stream
                float4 o = __ldcs(op + j);               // single-use (random)
                float4 d;
                d.x = a.x - o.x; d.y = a.y - o.y; d.z = a.z - o.z; d.w = a.w - o.w;
                __half2 lo = __floats2half2_rn(d.x, d.y);
                __half2 hi = __floats2half2_rn(d.z, d.w);
                pk[2*j]   = *(const unsigned int*)&lo;
                pk[2*j+1] = *(const unsigned int*)&hi;
                dot  += a.x*o.x + a.y*o.y + a.z*o.z + a.w*o.w;
                nin  += a.x*a.x + a.y*a.y + a.z*a.z + a.w*a.w;
                nold += o.x*o.x + o.y*o.y + o.z*o.z + o.w*o.w;
            }
            st_el_v8(df + (size_t)row * D + seg * 16, pk);   // pin in L2
        }

        #pragma unroll
        for (int off = 16; off > 0; off >>= 1) {
            dot  += __shfl_down_sync(0xffffffffu, dot,  off);
            nin  += __shfl_down_sync(0xffffffffu, nin,  off);
            nold += __shfl_down_sync(0xffffffffu, nold, off);
        }
        const int lane = threadIdx.x & 31;
        const int wid  = threadIdx.x >> 5;
        if (lane == 0) { s_red[0][wid] = dot; s_red[1][wid] = nin; s_red[2][wid] = nold; }
        __syncthreads();
        if (wid == 0) {
            const int nw = blockDim.x >> 5;
            float v0 = (lane < nw) ? s_red[0][lane] : 0.0f;
            float v1 = (lane < nw) ? s_red[1][lane] : 0.0f;
            float v2 = (lane < nw) ? s_red[2][lane] : 0.0f;
            #pragma unroll
            for (int off = 16; off > 0; off >>= 1) {
                v0 += __shfl_down_sync(0xffffffffu, v0, off);
                v1 += __shfl_down_sync(0xffffffffu, v1, off);
                v2 += __shfl_down_sync(0xffffffffu, v2, off);
            }
            if (lane == 0) {
                atomicAdd(&g_dots[0], v0);
                atomicAdd(&g_dots[1], v1);
                atomicAdd(&g_dots[2], v2);
                __threadfence();
                unsigned int t = atomicInc(&g_ticket, 0xffffffffu);
                if (t == GA - 1) {
                    volatile float* vd = g_dots;
                    float s0 = vd[0], s1 = vd[1], s2 = vd[2];
                    if (out_size > B * D)
                        out[B * D] = s0 / (sqrtf(s1) * sqrtf(s2));
                    vd[0] = 0.0f; vd[1] = 0.0f; vd[2] = 0.0f;
                    g_ticket = 0;
                }
            }
        }
    } else if (m5 <= 3) {
        // ---- Section B: convert old_activation -> fp16 (streaming reads).
        //      Each thread: 16 floats -> one 32B evict-last store. ----
        const int sb    = (blockIdx.x / 5) * 3 + (m5 - 1);
        const int tid   = sb * blockDim.x + threadIdx.x;
        const int nthr  = GB * blockDim.x;
        const int total = (ND * D) / 16;     // 16 floats per item
        const float4* src = (const float4*)old_act;

        for (int i = tid; i < total; i += nthr) {
            const float4* s4 = src + 4 * (size_t)i;
            unsigned int pk[8];
            #pragma unroll
            for (int j = 0; j < 4; j++) {
                float4 a = __ldcs(s4 + j);     // evict-first: don't pollute L2
                __half2 lo = __floats2half2_rn(a.x, a.y);
                __half2 hi = __floats2half2_rn(a.z, a.w);
                pk[2*j]   = *(const unsigned int*)&lo;
                pk[2*j+1] = *(const unsigned int*)&hi;
            }
            st_el_v8(g_src_h + (size_t)i * 16, pk);   // pin in L2
        }
    } else {
        // ---- Section C: bucket-fill both edge lists by output row.
        //      Stores PRECOMPUTED element offsets into g_src_h.
        //      (8B scattered stores can't be 256-bit -> default policy.) ----
        const int sb    = blockIdx.x / 5;
        const int tid   = sb * blockDim.x + threadIdx.x;
        const int nthr  = GC * blockDim.x;
        const int total = ESUB + ESUP;

        for (int e = tid; e < total; e += nthr) {
            int r, off; float v;
            if (e < ESUB) {
                r   = __ldcs(&sub_rows[e]);
                off = (ND + __ldcs(&sub_cols[e])) * D;   // diff region
                v   = __ldcs(&sub_vals[e]);
            } else {
                const int i = e - ESUB;
                r   = __ldcs(&sup_rows[i]);
                off = __ldcs(&sup_cols[i]) * D;          // old_act region
                v   = __ldcs(&sup_vals[i]);
            }
            const int pos = atomicAdd(&g_cnt[r], 1);
            if (pos < SLOTS) {
                int2 mm; mm.x = off; mm.y = __float_as_int(v);
                g_meta[(size_t)r * SLOTS + pos] = mm;
            }
        }
    }
}

// ---------------------------------------------------------------------------
// Row accumulation: one warp per output row, HALF-WARP per edge.
// 16 lanes x uint4 (8 halves) cover the 128-col source row -> one warp
// processes 2 edges per step, 4 independent row loads in flight.
// src lines were written evict-last by prep; plain loads here keep priority.
__global__ void __launch_bounds__(256) accumulate_kernel(
        float* __restrict__ out) {
    const int lane = threadIdx.x & 31;
    const int hw   = lane >> 4;        // half-warp id: 0 or 1
    const int hl   = lane & 15;        // lane within half-warp
    const int row  = blockIdx.x * 8 + (threadIdx.x >> 5);   // B % 8 == 0

    int deg = g_cnt[row];
    if (deg > SLOTS) deg = SLOTS;
    const int2* __restrict__ meta = g_meta + (size_t)row * SLOTS;

    float acc[8];
    #pragma unroll
    for (int j = 0; j < 8; j++) acc[j] = 0.0f;

    const int helem = hl * 8;   // this lane's 8-half slice within a row

    // 8 edges per iteration: 4 per half-warp, 4 LDG.128 in flight per lane.
    int k0 = 0;
    for (; k0 + 8 <= deg; k0 += 8) {
        uint4 s[4]; float vv[4];
        #pragma unroll
        for (int u = 0; u < 4; u++) {
            const int2 m = __ldg(&meta[k0 + 2 * u + hw]);
            vv[u] = __int_as_float(m.y);
            s[u]  = *(const uint4*)(g_src_h + m.x + helem);
        }
        #pragma unroll
        for (int u = 0; u < 4; u++) {
            float2 f0 = __half22float2(*(const __half2*)&s[u].x);
            float2 f1 = __half22float2(*(const __half2*)&s[u].y);
            float2 f2 = __half22float2(*(const __half2*)&s[u].z);
            float2 f3 = __half22float2(*(const __half2*)&s[u].w);
            acc[0] += f0.x * vv[u]; acc[1] += f0.y * vv[u];
            acc[2] += f1.x * vv[u]; acc[3] += f1.y * vv[u];
            acc[4] += f2.x * vv[u]; acc[5] += f2.y * vv[u];
            acc[6] += f3.x * vv[u]; acc[7] += f3.y * vv[u];
        }
    }
    // tail: 2 edges per step, predicated (v=0 lanes contribute nothing)
    for (; k0 < deg; k0 += 2) {
        const int k = k0 + hw;
        int  off = 0;
        float v  = 0.0f;
        if (k < deg) {
            const int2 m = __ldg(&meta[k]);
            off = m.x;
            v   = __int_as_float(m.y);
        }
        const uint4 s = *(const uint4*)(g_src_h + off + helem);
        float2 f0 = __half22float2(*(const __half2*)&s.x);
        float2 f1 = __half22float2(*(const __half2*)&s.y);
        float2 f2 = __half22float2(*(const __half2*)&s.z);
        float2 f3 = __half22float2(*(const __half2*)&s.w);
        acc[0] += f0.x * v; acc[1] += f0.y * v;
        acc[2] += f1.x * v; acc[3] += f1.y * v;
        acc[4] += f2.x * v; acc[5] += f2.y * v;
        acc[6] += f3.x * v; acc[7] += f3.y * v;
    }

    // merge the two half-warps (lane l and l^16 hold the same columns)
    #pragma unroll
    for (int j = 0; j < 8; j++)
        acc[j] += __shfl_xor_sync(0xffffffffu, acc[j], 16);

    // coalesced streaming store: full 512B row across the warp
    float4 o;
    if (hw == 0) { o.x = acc[0]; o.y = acc[1]; o.z = acc[2]; o.w = acc[3]; }
    else         { o.x = acc[4]; o.y = acc[5]; o.z = acc[6]; o.w = acc[7]; }
    __stcs((float4*)(out + (size_t)row * D + helem + hw * 4), o);

    // reset counter for the next graph replay (replaces a memset node)
    if (lane == 0) g_cnt[row] = 0;
}

// ---------------------------------------------------------------------------
extern "C" void kernel_launch(void* const* d_in, const int* in_sizes, int n_in,
                              void* d_out, int out_size) {
    const float* inputs   = (const float*)d_in[0];   // [B, D]
    const float* old_act  = (const float*)d_in[1];   // [ND, D]
    const int*   fields   = (const int*)  d_in[2];   // [B]
    const int*   sub_rows = (const int*)  d_in[3];   // [ESUB]
    const int*   sub_cols = (const int*)  d_in[4];
    const float* sub_vals = (const float*)d_in[5];
    const int*   sup_rows = (const int*)  d_in[6];   // [ESUP]
    const int*   sup_cols = (const int*)  d_in[7];
    const float* sup_vals = (const float*)d_in[8];
    float* out = (float*)d_out;

    // Zero only the tail of out beyond the accumulated region (accumulate
    // fully overwrites out[0 .. B*D); prep writes out[B*D]).
    if (out_size > B * D + 1) {
        cudaMemsetAsync(out + (B * D + 1), 0,
                        (size_t)(out_size - B * D - 1) * sizeof(float));
    }

    // Fused gather+convert+fill (g_cnt arrives zeroed: zero-init statics on
    // first call; accumulate_kernel re-zeros it at the end of every launch).
    prep_kernel<<<PREP_GRID, 256>>>(inputs, old_act, fields,
                                    sub_rows, sub_cols, sub_vals,
                                    sup_rows, sup_cols, sup_vals,
                                    out, out_size);

    // Register-accumulated SpMM over L2-pinned fp16 sources.
    accumulate_kernel<<<B / 8, 256>>>(out);
}

// round 15
// speedup vs baseline: 1.0292x; 1.0292x over previous
#include <cuda_runtime.h>
#include <cuda_fp16.h>
#include <math.h>

#define B     40000
#define D     128
#define D4    (D/4)
#define ND    200000
#define ESUB  320000
#define ESUP  1280000
#define SLOTS 128          // max edges per output row (mean 40, 14-sigma safe)

#define PREP_GRID 1184     // one full wave @ 8 blocks/SM x 148 SMs

// Scratch (static device globals — no allocation in kernel_launch)
// Single contiguous fp16 source matrix: rows [0, ND) = old_activation,
// rows [ND, ND+B) = diff. Fill precomputes element offsets into this array.
__device__ __half g_src_h[(size_t)(ND + B) * D];   // 61.4 MB
__device__ float g_dots[3];
__device__ unsigned int g_ticket = 0;
__device__ int  g_cnt[B];                    // zero-init; accumulate re-zeros
__device__ int2 g_meta[(size_t)B * SLOTS];   // (src_elem_offset, val_bits)

// ---------------------------------------------------------------------------
// Fused prep kernel: EVERY block runs all three sections sequentially as
// full-grid grid-stride loops (no inter-section dependency -> no syncs).
// This removes the straggler tail of a static block partition: all blocks
// finish within one loop-iteration of each other, and each memory-bound
// phase runs at full chip bandwidth.
// Single-use streams use __ldcs (evict-first).
__global__ void __launch_bounds__(256) prep_kernel(
        const float* __restrict__ inputs,
        const float* __restrict__ old_act,
        const int*   __restrict__ fields,
        const int*   __restrict__ sub_rows,
        const int*   __restrict__ sub_cols,
        const float* __restrict__ sub_vals,
        const int*   __restrict__ sup_rows,
        const int*   __restrict__ sup_cols,
        const float* __restrict__ sup_vals,
        float*       __restrict__ out,
        int out_size) {
    const int tid  = blockIdx.x * blockDim.x + threadIdx.x;
    const int nthr = gridDim.x * blockDim.x;

    // ---- Phase C: bucket-fill both edge lists by output row. ----
    {
        const int total = ESUB + ESUP;
        for (int e = tid; e < total; e += nthr) {
            int r, off; float v;
            if (e < ESUB) {
                r   = __ldcs(&sub_rows[e]);
                off = (ND + __ldcs(&sub_cols[e])) * D;   // diff region
                v   = __ldcs(&sub_vals[e]);
            } else {
                const int i = e - ESUB;
                r   = __ldcs(&sup_rows[i]);
                off = __ldcs(&sup_cols[i]) * D;          // old_act region
                v   = __ldcs(&sup_vals[i]);
            }
            const int pos = atomicAdd(&g_cnt[r], 1);
            if (pos < SLOTS) {
                int2 mm; mm.x = off; mm.y = __float_as_int(v);
                g_meta[(size_t)r * SLOTS + pos] = mm;
            }
        }
    }

    // ---- Phase A: gather old rows, diff (fp16 into g_src_h[ND..]),
    //      three dot products; last-finished block writes sim. ----
    {
        float dot = 0.0f, nin = 0.0f, nold = 0.0f;
        const float4* in4  = (const float4*)inputs;
        const float4* old4 = (const float4*)old_act;
        uint2*        df4  = (uint2*)(g_src_h + (size_t)ND * D);
        const int total = B * D4;

        for (int i = tid; i < total; i += nthr) {
            const int row = i >> 5;           // D4 == 32
            const int c4  = i & 31;
            const int f   = __ldg(&fields[row]);
            float4 a = __ldcs(&in4[i]);                       // single-use stream
            float4 o = __ldcs(&old4[(size_t)f * D4 + c4]);    // single-use (random)
            float4 d;
            d.x = a.x - o.x; d.y = a.y - o.y; d.z = a.z - o.z; d.w = a.w - o.w;
            __half2 lo = __floats2half2_rn(d.x, d.y);
            __half2 hi = __floats2half2_rn(d.z, d.w);
            uint2 packed;
            packed.x = *(const unsigned int*)&lo;
            packed.y = *(const unsigned int*)&hi;
            df4[i] = packed;
            dot  += a.x*o.x + a.y*o.y + a.z*o.z + a.w*o.w;
            nin  += a.x*a.x + a.y*a.y + a.z*a.z + a.w*a.w;
            nold += o.x*o.x + o.y*o.y + o.z*o.z + o.w*o.w;
        }

        __shared__ float s_red[3][8];
        #pragma unroll
        for (int off = 16; off > 0; off >>= 1) {
            dot  += __shfl_down_sync(0xffffffffu, dot,  off);
            nin  += __shfl_down_sync(0xffffffffu, nin,  off);
            nold += __shfl_down_sync(0xffffffffu, nold, off);
        }
        const int lane = threadIdx.x & 31;
        const int wid  = threadIdx.x >> 5;
        if (lane == 0) { s_red[0][wid] = dot; s_red[1][wid] = nin; s_red[2][wid] = nold; }
        __syncthreads();
        if (wid == 0) {
            const int nw = blockDim.x >> 5;
            float v0 = (lane < nw) ? s_red[0][lane] : 0.0f;
            float v1 = (lane < nw) ? s_red[1][lane] : 0.0f;
            float v2 = (lane < nw) ? s_red[2][lane] : 0.0f;
            #pragma unroll
            for (int off = 16; off > 0; off >>= 1) {
                v0 += __shfl_down_sync(0xffffffffu, v0, off);
                v1 += __shfl_down_sync(0xffffffffu, v1, off);
                v2 += __shfl_down_sync(0xffffffffu, v2, off);
            }
            if (lane == 0) {
                atomicAdd(&g_dots[0], v0);
                atomicAdd(&g_dots[1], v1);
                atomicAdd(&g_dots[2], v2);
                __threadfence();
                unsigned int t = atomicInc(&g_ticket, 0xffffffffu);
                if (t == gridDim.x - 1) {
                    volatile float* vd = g_dots;
                    float s0 = vd[0], s1 = vd[1], s2 = vd[2];
                    if (out_size > B * D)
                        out[B * D] = s0 / (sqrtf(s1) * sqrtf(s2));
                    vd[0] = 0.0f; vd[1] = 0.0f; vd[2] = 0.0f;
                    g_ticket = 0;
                }
            }
        }
    }

    // ---- Phase B: convert old_activation -> fp16 (streaming). ----
    {
        const int total = (ND * D) / 8;      // 8 floats per item
        const float4* src = (const float4*)old_act;
        uint4*        dst = (uint4*)g_src_h;

        for (int i = tid; i < total; i += nthr) {
            float4 a = __ldcs(&src[2 * i]);        // evict-first stream
            float4 b = __ldcs(&src[2 * i + 1]);
            __half2 h0 = __floats2half2_rn(a.x, a.y);
            __half2 h1 = __floats2half2_rn(a.z, a.w);
            __half2 h2 = __floats2half2_rn(b.x, b.y);
            __half2 h3 = __floats2half2_rn(b.z, b.w);
            uint4 p;
            p.x = *(const unsigned int*)&h0;
            p.y = *(const unsigned int*)&h1;
            p.z = *(const unsigned int*)&h2;
            p.w = *(const unsigned int*)&h3;
            dst[i] = p;
        }
    }
}

// ---------------------------------------------------------------------------
// Row accumulation: one warp per output row, HALF-WARP per edge.
// 16 lanes x uint4 (8 halves) cover the 128-col source row -> one warp
// processes 2 edges per step, 4 independent row loads in flight.
// Single coalesced float4 store per row; resets g_cnt[row] for next replay.
__global__ void __launch_bounds__(256) accumulate_kernel(
        float* __restrict__ out) {
    const int lane = threadIdx.x & 31;
    const int hw   = lane >> 4;        // half-warp id: 0 or 1
    const int hl   = lane & 15;        // lane within half-warp
    const int row  = blockIdx.x * 8 + (threadIdx.x >> 5);   // B % 8 == 0

    int deg = g_cnt[row];
    if (deg > SLOTS) deg = SLOTS;
    const int2* __restrict__ meta = g_meta + (size_t)row * SLOTS;

    float acc[8];
    #pragma unroll
    for (int j = 0; j < 8; j++) acc[j] = 0.0f;

    const int helem = hl * 8;   // this lane's 8-half slice within a row

    // 8 edges per iteration: 4 per half-warp, 4 LDG.128 in flight per lane.
    int k0 = 0;
    for (; k0 + 8 <= deg; k0 += 8) {
        uint4 s[4]; float vv[4];
        #pragma unroll
        for (int u = 0; u < 4; u++) {
            const int2 m = __ldg(&meta[k0 + 2 * u + hw]);
            vv[u] = __int_as_float(m.y);
            s[u]  = *(const uint4*)(g_src_h + m.x + helem);
        }
        #pragma unroll
        for (int u = 0; u < 4; u++) {
            float2 f0 = __half22float2(*(const __half2*)&s[u].x);
            float2 f1 = __half22float2(*(const __half2*)&s[u].y);
            float2 f2 = __half22float2(*(const __half2*)&s[u].z);
            float2 f3 = __half22float2(*(const __half2*)&s[u].w);
            acc[0] += f0.x * vv[u]; acc[1] += f0.y * vv[u];
            acc[2] += f1.x * vv[u]; acc[3] += f1.y * vv[u];
            acc[4] += f2.x * vv[u]; acc[5] += f2.y * vv[u];
            acc[6] += f3.x * vv[u]; acc[7] += f3.y * vv[u];
        }
    }
    // tail: 2 edges per step, predicated (v=0 lanes contribute nothing)
    for (; k0 < deg; k0 += 2) {
        const int k = k0 + hw;
        int  off = 0;
        float v  = 0.0f;
        if (k < deg) {
            const int2 m = __ldg(&meta[k]);
            off = m.x;
            v   = __int_as_float(m.y);
        }
        const uint4 s = *(const uint4*)(g_src_h + off + helem);
        float2 f0 = __half22float2(*(const __half2*)&s.x);
        float2 f1 = __half22float2(*(const __half2*)&s.y);
        float2 f2 = __half22float2(*(const __half2*)&s.z);
        float2 f3 = __half22float2(*(const __half2*)&s.w);
        acc[0] += f0.x * v; acc[1] += f0.y * v;
        acc[2] += f1.x * v; acc[3] += f1.y * v;
        acc[4] += f2.x * v; acc[5] += f2.y * v;
        acc[6] += f3.x * v; acc[7] += f3.y * v;
    }

    // merge the two half-warps (lane l and l^16 hold the same columns)
    #pragma unroll
    for (int j = 0; j < 8; j++)
        acc[j] += __shfl_xor_sync(0xffffffffu, acc[j], 16);

    // coalesced streaming store: full 512B row across the warp
    float4 o;
    if (hw == 0) { o.x = acc[0]; o.y = acc[1]; o.z = acc[2]; o.w = acc[3]; }
    else         { o.x = acc[4]; o.y = acc[5]; o.z = acc[6]; o.w = acc[7]; }
    __stcs((float4*)(out + (size_t)row * D + helem + hw * 4), o);

    // reset counter for the next graph replay (replaces a memset node)
    if (lane == 0) g_cnt[row] = 0;
}

// ---------------------------------------------------------------------------
extern "C" void kernel_launch(void* const* d_in, const int* in_sizes, int n_in,
                              void* d_out, int out_size) {
    const float* inputs   = (const float*)d_in[0];   // [B, D]
    const float* old_act  = (const float*)d_in[1];   // [ND, D]
    const int*   fields   = (const int*)  d_in[2];   // [B]
    const int*   sub_rows = (const int*)  d_in[3];   // [ESUB]
    const int*   sub_cols = (const int*)  d_in[4];
    const float* sub_vals = (const float*)d_in[5];
    const int*   sup_rows = (const int*)  d_in[6];   // [ESUP]
    const int*   sup_cols = (const int*)  d_in[7];
    const float* sup_vals = (const float*)d_in[8];
    float* out = (float*)d_out;

    // Zero only the tail of out beyond the accumulated region (accumulate
    // fully overwrites out[0 .. B*D); prep writes out[B*D]).
    if (out_size > B * D + 1) {
        cudaMemsetAsync(out + (B * D + 1), 0,
                        (size_t)(out_size - B * D - 1) * sizeof(float));
    }

    // Fused gather+convert+fill (g_cnt arrives zeroed: zero-init statics on
    // first call; accumulate_kernel re-zeros it at the end of every launch).
    prep_kernel<<<PREP_GRID, 256>>>(inputs, old_act, fields,
                                    sub_rows, sub_cols, sub_vals,
                                    sup_rows, sup_cols, sup_vals,
                                    out, out_size);

    // Register-accumulated SpMM over fp16 sources.
    accumulate_kernel<<<B / 8, 256>>>(out);
}

// round 16
// speedup vs baseline: 1.0929x; 1.0620x over previous
#include <cuda_runtime.h>
#include <cuda_fp16.h>
#include <math.h>

#define B     40000
#define D     128
#define D4    (D/4)
#define ND    200000
#define ESUB  320000
#define ESUP  1280000
#define ETOT  (ESUB + ESUP)
#define SLOTS 128          // max edges per output row (mean 40, 14-sigma safe)

#define PREP_GRID 1184     // one full wave @ 8 blocks/SM x 148 SMs
#define PREP_THREADS 256

// Chunking for dynamic work-stealing (1024 items per chunk, 4 per thread)
#define CH_ITEMS 1024
#define NCH_A (B * D4 / CH_ITEMS)          // 1250  (uint2 diff items)
#define NCH_B ((ND * D / 8) / CH_ITEMS)    // 3125  (8-float convert items)
#define NCH_C ((ETOT + CH_ITEMS - 1) / CH_ITEMS)  // 1563 (edges)

// Scratch (static device globals — no allocation in kernel_launch)
// Single contiguous fp16 source matrix: rows [0, ND) = old_activation,
// rows [ND, ND+B) = diff. Fill precomputes element offsets into this array.
__device__ __half g_src_h[(size_t)(ND + B) * D];   // 61.4 MB
__device__ float g_dots[3];
__device__ unsigned int g_ticket = 0;
__device__ int  g_cnt[B];                    // zero-init; accumulate re-zeros
__device__ int2 g_meta[(size_t)B * SLOTS];   // (src_elem_offset, val_bits)
__device__ unsigned int g_wA = 0, g_wB = 0, g_wC = 0;  // chunk counters

// ---------------------------------------------------------------------------
// Fused prep kernel with dynamic chunk-stealing across three CONCURRENT
// phases (A: gather/diff/dots, B: fp16 convert, C: bucket fill). Blocks
// start on a weighted round-robin phase and migrate when a phase runs out,
// so no SM idles while any phase has work (removes the static-split tail).
// Single-use streams use __ldcs (evict-first).
__global__ void __launch_bounds__(PREP_THREADS) prep_kernel(
        const float* __restrict__ inputs,
        const float* __restrict__ old_act,
        const int*   __restrict__ fields,
        const int*   __restrict__ sub_rows,
        const int*   __restrict__ sub_cols,
        const float* __restrict__ sub_vals,
        const int*   __restrict__ sup_rows,
        const int*   __restrict__ sup_cols,
        const float* __restrict__ sup_vals,
        float*       __restrict__ out,
        int out_size) {
    __shared__ unsigned int s_chunk;
    __shared__ int s_done;                 // bitmask of exhausted phases

    const int t = threadIdx.x;

    // phase-A accumulators (kept across stolen A-chunks)
    float dot = 0.0f, nin = 0.0f, nold = 0.0f;

    const float4* in4  = (const float4*)inputs;
    const float4* old4 = (const float4*)old_act;
    uint2*        df4  = (uint2*)(g_src_h + (size_t)ND * D);
    const float4* cb   = (const float4*)old_act;
    uint4*        dst  = (uint4*)g_src_h;

    // starting phase: B gets double weight
    int phase = blockIdx.x & 3;            // 0:A 1:B 2:C 3:B
    if (phase == 3) phase = 1;
    if (t == 0) s_done = 0;
    __syncthreads();

    for (;;) {
        if (t == 0) {
            // steal a chunk from the current phase; mark exhaustion
            unsigned int c = 0xffffffffu;
            if (phase == 0) {
                c = atomicAdd(&g_wA, 1u);
                if (c >= NCH_A) { s_done |= 1; c = 0xffffffffu; }
            } else if (phase == 1) {
                c = atomicAdd(&g_wB, 1u);
                if (c >= NCH_B) { s_done |= 2; c = 0xffffffffu; }
            } else {
                c = atomicAdd(&g_wC, 1u);
                if (c >= NCH_C) { s_done |= 4; c = 0xffffffffu; }
            }
            s_chunk = c;
        }
        __syncthreads();
        const unsigned int chunk = s_chunk;
        const int done = s_done;
        __syncthreads();   // protect s_chunk before next steal

        if (chunk == 0xffffffffu) {
            if (done == 7) break;          // all phases drained
            // migrate to next unfinished phase
            do { phase = (phase + 1) % 3; } while (done & (1 << phase));
            continue;
        }

        const int base = (int)chunk * CH_ITEMS + t;

        if (phase == 0) {
            // ---- A: gather + diff(fp16) + dot partials ----
            #pragma unroll
            for (int k = 0; k < 4; k++) {
                const int i   = base + k * PREP_THREADS;
                const int row = i >> 5;                 // D4 == 32
                const int c4  = i & 31;
                const int f   = __ldg(&fields[row]);
                float4 a = __ldcs(&in4[i]);
                float4 o = __ldcs(&old4[(size_t)f * D4 + c4]);
                float4 d;
                d.x = a.x - o.x; d.y = a.y - o.y; d.z = a.z - o.z; d.w = a.w - o.w;
                __half2 lo = __floats2half2_rn(d.x, d.y);
                __half2 hi = __floats2half2_rn(d.z, d.w);
                uint2 packed;
                packed.x = *(const unsigned int*)&lo;
                packed.y = *(const unsigned int*)&hi;
                df4[i] = packed;
                dot  += a.x*o.x + a.y*o.y + a.z*o.z + a.w*o.w;
                nin  += a.x*a.x + a.y*a.y + a.z*a.z + a.w*a.w;
                nold += o.x*o.x + o.y*o.y + o.z*o.z + o.w*o.w;
            }
        } else if (phase == 1) {
            // ---- B: convert old_activation -> fp16 (streaming) ----
            #pragma unroll
            for (int k = 0; k < 4; k++) {
                const int i = base + k * PREP_THREADS;
                float4 a = __ldcs(&cb[2 * (size_t)i]);
                float4 b = __ldcs(&cb[2 * (size_t)i + 1]);
                __half2 h0 = __floats2half2_rn(a.x, a.y);
                __half2 h1 = __floats2half2_rn(a.z, a.w);
                __half2 h2 = __floats2half2_rn(b.x, b.y);
                __half2 h3 = __floats2half2_rn(b.z, b.w);
                uint4 p;
                p.x = *(const unsigned int*)&h0;
                p.y = *(const unsigned int*)&h1;
                p.z = *(const unsigned int*)&h2;
                p.w = *(const unsigned int*)&h3;
                dst[i] = p;
            }
        } else {
            // ---- C: bucket-fill both edge lists by output row ----
            #pragma unroll
            for (int k = 0; k < 4; k++) {
                const int e = base + k * PREP_THREADS;
                if (e >= ETOT) continue;
                int r, off; float v;
                if (e < ESUB) {
                    r   = __ldcs(&sub_rows[e]);
                    off = (ND + __ldcs(&sub_cols[e])) * D;   // diff region
                    v   = __ldcs(&sub_vals[e]);
                } else {
                    const int i = e - ESUB;
                    r   = __ldcs(&sup_rows[i]);
                    off = __ldcs(&sup_cols[i]) * D;          // old_act region
                    v   = __ldcs(&sup_vals[i]);
                }
                const int pos = atomicAdd(&g_cnt[r], 1);
                if (pos < SLOTS) {
                    int2 mm; mm.x = off; mm.y = __float_as_int(v);
                    g_meta[(size_t)r * SLOTS + pos] = mm;
                }
            }
        }
    }

    // ---- dot-product reduction + sim finalizer (every block contributes) --
    __shared__ float s_red[3][8];
    #pragma unroll
    for (int off = 16; off > 0; off >>= 1) {
        dot  += __shfl_down_sync(0xffffffffu, dot,  off);
        nin  += __shfl_down_sync(0xffffffffu, nin,  off);
        nold += __shfl_down_sync(0xffffffffu, nold, off);
    }
    const int lane = t & 31;
    const int wid  = t >> 5;
    if (lane == 0) { s_red[0][wid] = dot; s_red[1][wid] = nin; s_red[2][wid] = nold; }
    __syncthreads();
    if (wid == 0) {
        const int nw = PREP_THREADS >> 5;
        float v0 = (lane < nw) ? s_red[0][lane] : 0.0f;
        float v1 = (lane < nw) ? s_red[1][lane] : 0.0f;
        float v2 = (lane < nw) ? s_red[2][lane] : 0.0f;
        #pragma unroll
        for (int off = 16; off > 0; off >>= 1) {
            v0 += __shfl_down_sync(0xffffffffu, v0, off);
            v1 += __shfl_down_sync(0xffffffffu, v1, off);
            v2 += __shfl_down_sync(0xffffffffu, v2, off);
        }
        if (lane == 0) {
            atomicAdd(&g_dots[0], v0);
            atomicAdd(&g_dots[1], v1);
            atomicAdd(&g_dots[2], v2);
            __threadfence();
            unsigned int tk = atomicInc(&g_ticket, 0xffffffffu);
            if (tk == gridDim.x - 1) {
                volatile float* vd = g_dots;
                float s0 = vd[0], s1 = vd[1], s2 = vd[2];
                if (out_size > B * D)
                    out[B * D] = s0 / (sqrtf(s1) * sqrtf(s2));
                vd[0] = 0.0f; vd[1] = 0.0f; vd[2] = 0.0f;
                g_ticket = 0;
            }
        }
    }
}

// ---------------------------------------------------------------------------
// Row accumulation: one warp per output row, HALF-WARP per edge.
// 16 lanes x uint4 (8 halves) cover the 128-col source row -> one warp
// processes 2 edges per step, 4 independent row loads in flight.
// Single coalesced float4 store per row; resets g_cnt + work counters.
__global__ void __launch_bounds__(256) accumulate_kernel(
        float* __restrict__ out) {
    const int lane = threadIdx.x & 31;
    const int hw   = lane >> 4;        // half-warp id: 0 or 1
    const int hl   = lane & 15;        // lane within half-warp
    const int row  = blockIdx.x * 8 + (threadIdx.x >> 5);   // B % 8 == 0

    int deg = g_cnt[row];
    if (deg > SLOTS) deg = SLOTS;
    const int2* __restrict__ meta = g_meta + (size_t)row * SLOTS;

    float acc[8];
    #pragma unroll
    for (int j = 0; j < 8; j++) acc[j] = 0.0f;

    const int helem = hl * 8;   // this lane's 8-half slice within a row

    // 8 edges per iteration: 4 per half-warp, 4 LDG.128 in flight per lane.
    int k0 = 0;
    for (; k0 + 8 <= deg; k0 += 8) {
        uint4 s[4]; float vv[4];
        #pragma unroll
        for (int u = 0; u < 4; u++) {
            const int2 m = __ldg(&meta[k0 + 2 * u + hw]);
            vv[u] = __int_as_float(m.y);
            s[u]  = *(const uint4*)(g_src_h + m.x + helem);
        }
        #pragma unroll
        for (int u = 0; u < 4; u++) {
            float2 f0 = __half22float2(*(const __half2*)&s[u].x);
            float2 f1 = __half22float2(*(const __half2*)&s[u].y);
            float2 f2 = __half22float2(*(const __half2*)&s[u].z);
            float2 f3 = __half22float2(*(const __half2*)&s[u].w);
            acc[0] += f0.x * vv[u]; acc[1] += f0.y * vv[u];
            acc[2] += f1.x * vv[u]; acc[3] += f1.y * vv[u];
            acc[4] += f2.x * vv[u]; acc[5] += f2.y * vv[u];
            acc[6] += f3.x * vv[u]; acc[7] += f3.y * vv[u];
        }
    }
    // tail: 2 edges per step, predicated (v=0 lanes contribute nothing)
    for (; k0 < deg; k0 += 2) {
        const int k = k0 + hw;
        int  off = 0;
        float v  = 0.0f;
        if (k < deg) {
            const int2 m = __ldg(&meta[k]);
            off = m.x;
            v   = __int_as_float(m.y);
        }
        const uint4 s = *(const uint4*)(g_src_h + off + helem);
        float2 f0 = __half22float2(*(const __half2*)&s.x);
        float2 f1 = __half22float2(*(const __half2*)&s.y);
        float2 f2 = __half22float2(*(const __half2*)&s.z);
        float2 f3 = __half22float2(*(const __half2*)&s.w);
        acc[0] += f0.x * v; acc[1] += f0.y * v;
        acc[2] += f1.x * v; acc[3] += f1.y * v;
        acc[4] += f2.x * v; acc[5] += f2.y * v;
        acc[6] += f3.x * v; acc[7] += f3.y * v;
    }

    // merge the two half-warps (lane l and l^16 hold the same columns)
    #pragma unroll
    for (int j = 0; j < 8; j++)
        acc[j] += __shfl_xor_sync(0xffffffffu, acc[j], 16);

    // coalesced streaming store: full 512B row across the warp
    float4 o;
    if (hw == 0) { o.x = acc[0]; o.y = acc[1]; o.z = acc[2]; o.w = acc[3]; }
    else         { o.x = acc[4]; o.y = acc[5]; o.z = acc[6]; o.w = acc[7]; }
    __stcs((float4*)(out + (size_t)row * D + helem + hw * 4), o);

    // reset per-row counter and (one thread) the work-steal counters so the
    // next graph replay starts from clean state
    if (lane == 0) g_cnt[row] = 0;
    if (blockIdx.x == 0 && threadIdx.x == 0) {
        g_wA = 0; g_wB = 0; g_wC = 0;
    }
}

// ---------------------------------------------------------------------------
extern "C" void kernel_launch(void* const* d_in, const int* in_sizes, int n_in,
                              void* d_out, int out_size) {
    const float* inputs   = (const float*)d_in[0];   // [B, D]
    const float* old_act  = (const float*)d_in[1];   // [ND, D]
    const int*   fields   = (const int*)  d_in[2];   // [B]
    const int*   sub_rows = (const int*)  d_in[3];   // [ESUB]
    const int*   sub_cols = (const int*)  d_in[4];
    const float* sub_vals = (const float*)d_in[5];
    const int*   sup_rows = (const int*)  d_in[6];   // [ESUP]
    const int*   sup_cols = (const int*)  d_in[7];
    const float* sup_vals = (const float*)d_in[8];
    float* out = (float*)d_out;

    // Zero only the tail of out beyond the accumulated region (accumulate
    // fully overwrites out[0 .. B*D); prep writes out[B*D]).
    if (out_size > B * D + 1) {
        cudaMemsetAsync(out + (B * D + 1), 0,
                        (size_t)(out_size - B * D - 1) * sizeof(float));
    }

    // Fused gather+convert+fill with dynamic chunk-stealing (counters arrive
    // zeroed: zero-init statics on first call; accumulate re-zeros them).
    prep_kernel<<<PREP_GRID, PREP_THREADS>>>(inputs, old_act, fields,
                                             sub_rows, sub_cols, sub_vals,
                                             sup_rows, sup_cols, sup_vals,
                                             out, out_size);

    // Register-accumulated SpMM over fp16 sources.
    accumulate_kernel<<<B / 8, 256>>>(out);
}

// round 17
// speedup vs baseline: 1.1084x; 1.0142x over previous
#include <cuda_runtime.h>
#include <cuda_fp16.h>
#include <math.h>

#define B     40000
#define D     128
#define D4    (D/4)
#define ND    200000
#define ESUB  320000
#define ESUP  1280000
#define ETOT  (ESUB + ESUP)
#define SLOTS 128          // max edges per output row (mean 40, 14-sigma safe)

#define PREP_GRID 1184     // one full wave @ 8 blocks/SM x 148 SMs
#define PREP_THREADS 256

// Chunking for dynamic work-stealing (1024 items per chunk, 4 per thread)
#define CH_ITEMS 1024
#define NCH_A (B * D4 / CH_ITEMS)          // 1250  (uint2 diff items)
#define NCH_B ((ND * D / 8) / CH_ITEMS)    // 3125  (8-float convert items)
#define NCH_C ((ETOT + CH_ITEMS - 1) / CH_ITEMS)  // 1563 (edges)

// Scratch (static device globals — no allocation in kernel_launch)
// Single contiguous fp16 source matrix: rows [0, ND) = old_activation,
// rows [ND, ND+B) = diff. Fill precomputes element offsets into this array.
__device__ __half g_src_h[(size_t)(ND + B) * D];   // 61.4 MB
__device__ float g_dots[3];
__device__ unsigned int g_ticket = 0;
__device__ int  g_cnt[B];                    // zero-init; accumulate re-zeros
__device__ int2 g_meta[(size_t)B * SLOTS];   // (src_elem_offset, val_bits)
__device__ unsigned int g_wA = 0, g_wB = 0, g_wC = 0;  // chunk counters

// ---------------------------------------------------------------------------
// Fused prep kernel with dynamic chunk-stealing across three CONCURRENT
// phases (A: gather/diff/dots, B: fp16 convert, C: bucket fill).
// Scratch working-set stores (g_src_h, g_meta) use WRITE-THROUGH (__stwt):
// the DRAM write happens here, during prep's DRAM headroom, leaving the L2
// lines CLEAN so the LTS-bound accumulate kernel pays no dirty writebacks.
// Single-use streams use __ldcs (evict-first).
__global__ void __launch_bounds__(PREP_THREADS) prep_kernel(
        const float* __restrict__ inputs,
        const float* __restrict__ old_act,
        const int*   __restrict__ fields,
        const int*   __restrict__ sub_rows,
        const int*   __restrict__ sub_cols,
        const float* __restrict__ sub_vals,
        const int*   __restrict__ sup_rows,
        const int*   __restrict__ sup_cols,
        const float* __restrict__ sup_vals,
        float*       __restrict__ out,
        int out_size) {
    __shared__ unsigned int s_chunk;
    __shared__ int s_done;                 // bitmask of exhausted phases

    const int t = threadIdx.x;

    // phase-A accumulators (kept across stolen A-chunks)
    float dot = 0.0f, nin = 0.0f, nold = 0.0f;

    const float4* in4  = (const float4*)inputs;
    const float4* old4 = (const float4*)old_act;
    uint2*        df4  = (uint2*)(g_src_h + (size_t)ND * D);
    const float4* cb   = (const float4*)old_act;
    uint4*        dst  = (uint4*)g_src_h;

    // starting phase: B gets double weight
    int phase = blockIdx.x & 3;            // 0:A 1:B 2:C 3:B
    if (phase == 3) phase = 1;
    if (t == 0) s_done = 0;
    __syncthreads();

    for (;;) {
        if (t == 0) {
            // steal a chunk from the current phase; mark exhaustion
            unsigned int c = 0xffffffffu;
            if (phase == 0) {
                c = atomicAdd(&g_wA, 1u);
                if (c >= NCH_A) { s_done |= 1; c = 0xffffffffu; }
            } else if (phase == 1) {
                c = atomicAdd(&g_wB, 1u);
                if (c >= NCH_B) { s_done |= 2; c = 0xffffffffu; }
            } else {
                c = atomicAdd(&g_wC, 1u);
                if (c >= NCH_C) { s_done |= 4; c = 0xffffffffu; }
            }
            s_chunk = c;
        }
        __syncthreads();
        const unsigned int chunk = s_chunk;
        const int done = s_done;
        __syncthreads();   // protect s_chunk before next steal

        if (chunk == 0xffffffffu) {
            if (done == 7) break;          // all phases drained
            // migrate to next unfinished phase
            do { phase = (phase + 1) % 3; } while (done & (1 << phase));
            continue;
        }

        const int base = (int)chunk * CH_ITEMS + t;

        if (phase == 0) {
            // ---- A: gather + diff(fp16) + dot partials ----
            #pragma unroll
            for (int k = 0; k < 4; k++) {
                const int i   = base + k * PREP_THREADS;
                const int row = i >> 5;                 // D4 == 32
                const int c4  = i & 31;
                const int f   = __ldg(&fields[row]);
                float4 a = __ldcs(&in4[i]);
                float4 o = __ldcs(&old4[(size_t)f * D4 + c4]);
                float4 d;
                d.x = a.x - o.x; d.y = a.y - o.y; d.z = a.z - o.z; d.w = a.w - o.w;
                __half2 lo = __floats2half2_rn(d.x, d.y);
                __half2 hi = __floats2half2_rn(d.z, d.w);
                uint2 packed;
                packed.x = *(const unsigned int*)&lo;
                packed.y = *(const unsigned int*)&hi;
                __stwt(&df4[i], packed);               // write-through: clean line
                dot  += a.x*o.x + a.y*o.y + a.z*o.z + a.w*o.w;
                nin  += a.x*a.x + a.y*a.y + a.z*a.z + a.w*a.w;
                nold += o.x*o.x + o.y*o.y + o.z*o.z + o.w*o.w;
            }
        } else if (phase == 1) {
            // ---- B: convert old_activation -> fp16 (streaming) ----
            #pragma unroll
            for (int k = 0; k < 4; k++) {
                const int i = base + k * PREP_THREADS;
                float4 a = __ldcs(&cb[2 * (size_t)i]);
                float4 b = __ldcs(&cb[2 * (size_t)i + 1]);
                __half2 h0 = __floats2half2_rn(a.x, a.y);
                __half2 h1 = __floats2half2_rn(a.z, a.w);
                __half2 h2 = __floats2half2_rn(b.x, b.y);
                __half2 h3 = __floats2half2_rn(b.z, b.w);
                uint4 p;
                p.x = *(const unsigned int*)&h0;
                p.y = *(const unsigned int*)&h1;
                p.z = *(const unsigned int*)&h2;
                p.w = *(const unsigned int*)&h3;
                __stwt(&dst[i], p);                    // write-through: clean line
            }
        } else {
            // ---- C: bucket-fill both edge lists by output row ----
            #pragma unroll
            for (int k = 0; k < 4; k++) {
                const int e = base + k * PREP_THREADS;
                if (e >= ETOT) continue;
                int r, off; float v;
                if (e < ESUB) {
                    r   = __ldcs(&sub_rows[e]);
                    off = (ND + __ldcs(&sub_cols[e])) * D;   // diff region
                    v   = __ldcs(&sub_vals[e]);
                } else {
                    const int i = e - ESUB;
                    r   = __ldcs(&sup_rows[i]);
                    off = __ldcs(&sup_cols[i]) * D;          // old_act region
                    v   = __ldcs(&sup_vals[i]);
                }
                const int pos = atomicAdd(&g_cnt[r], 1);
                if (pos < SLOTS) {
                    int2 mm; mm.x = off; mm.y = __float_as_int(v);
                    __stwt(&g_meta[(size_t)r * SLOTS + pos], mm);  // clean line
                }
            }
        }
    }

    // ---- dot-product reduction + sim finalizer (every block contributes) --
    __shared__ float s_red[3][8];
    #pragma unroll
    for (int off = 16; off > 0; off >>= 1) {
        dot  += __shfl_down_sync(0xffffffffu, dot,  off);
        nin  += __shfl_down_sync(0xffffffffu, nin,  off);
        nold += __shfl_down_sync(0xffffffffu, nold, off);
    }
    const int lane = t & 31;
    const int wid  = t >> 5;
    if (lane == 0) { s_red[0][wid] = dot; s_red[1][wid] = nin; s_red[2][wid] = nold; }
    __syncthreads();
    if (wid == 0) {
        const int nw = PREP_THREADS >> 5;
        float v0 = (lane < nw) ? s_red[0][lane] : 0.0f;
        float v1 = (lane < nw) ? s_red[1][lane] : 0.0f;
        float v2 = (lane < nw) ? s_red[2][lane] : 0.0f;
        #pragma unroll
        for (int off = 16; off > 0; off >>= 1) {
            v0 += __shfl_down_sync(0xffffffffu, v0, off);
            v1 += __shfl_down_sync(0xffffffffu, v1, off);
            v2 += __shfl_down_sync(0xffffffffu, v2, off);
        }
        if (lane == 0) {
            atomicAdd(&g_dots[0], v0);
            atomicAdd(&g_dots[1], v1);
            atomicAdd(&g_dots[2], v2);
            __threadfence();
            unsigned int tk = atomicInc(&g_ticket, 0xffffffffu);
            if (tk == gridDim.x - 1) {
                volatile float* vd = g_dots;
                float s0 = vd[0], s1 = vd[1], s2 = vd[2];
                if (out_size > B * D)
                    out[B * D] = s0 / (sqrtf(s1) * sqrtf(s2));
                vd[0] = 0.0f; vd[1] = 0.0f; vd[2] = 0.0f;
                g_ticket = 0;
            }
        }
    }
}

// ---------------------------------------------------------------------------
// Row accumulation: one warp per output row, HALF-WARP per edge.
// 16 lanes x uint4 (8 halves) cover the 128-col source row -> one warp
// processes 2 edges per step, 4 independent row loads in flight.
// Single coalesced float4 store per row; resets g_cnt + work counters.
__global__ void __launch_bounds__(256) accumulate_kernel(
        float* __restrict__ out) {
    const int lane = threadIdx.x & 31;
    const int hw   = lane >> 4;        // half-warp id: 0 or 1
    const int hl   = lane & 15;        // lane within half-warp
    const int row  = blockIdx.x * 8 + (threadIdx.x >> 5);   // B % 8 == 0

    int deg = g_cnt[row];
    if (deg > SLOTS) deg = SLOTS;
    const int2* __restrict__ meta = g_meta + (size_t)row * SLOTS;

    float acc[8];
    #pragma unroll
    for (int j = 0; j < 8; j++) acc[j] = 0.0f;

    const int helem = hl * 8;   // this lane's 8-half slice within a row

    // 8 edges per iteration: 4 per half-warp, 4 LDG.128 in flight per lane.
    int k0 = 0;
    for (; k0 + 8 <= deg; k0 += 8) {
        uint4 s[4]; float vv[4];
        #pragma unroll
        for (int u = 0; u < 4; u++) {
            const int2 m = __ldg(&meta[k0 + 2 * u + hw]);
            vv[u] = __int_as_float(m.y);
            s[u]  = *(const uint4*)(g_src_h + m.x + helem);
        }
        #pragma unroll
        for (int u = 0; u < 4; u++) {
            float2 f0 = __half22float2(*(const __half2*)&s[u].x);
            float2 f1 = __half22float2(*(const __half2*)&s[u].y);
            float2 f2 = __half22float2(*(const __half2*)&s[u].z);
            float2 f3 = __half22float2(*(const __half2*)&s[u].w);
            acc[0] += f0.x * vv[u]; acc[1] += f0.y * vv[u];
            acc[2] += f1.x * vv[u]; acc[3] += f1.y * vv[u];
            acc[4] += f2.x * vv[u]; acc[5] += f2.y * vv[u];
            acc[6] += f3.x * vv[u]; acc[7] += f3.y * vv[u];
        }
    }
    // tail: 2 edges per step, predicated (v=0 lanes contribute nothing)
    for (; k0 < deg; k0 += 2) {
        const int k = k0 + hw;
        int  off = 0;
        float v  = 0.0f;
        if (k < deg) {
            const int2 m = __ldg(&meta[k]);
            off = m.x;
            v   = __int_as_float(m.y);
        }
        const uint4 s = *(const uint4*)(g_src_h + off + helem);
        float2 f0 = __half22float2(*(const __half2*)&s.x);
        float2 f1 = __half22float2(*(const __half2*)&s.y);
        float2 f2 = __half22float2(*(const __half2*)&s.z);
        float2 f3 = __half22float2(*(const __half2*)&s.w);
        acc[0] += f0.x * v; acc[1] += f0.y * v;
        acc[2] += f1.x * v; acc[3] += f1.y * v;
        acc[4] += f2.x * v; acc[5] += f2.y * v;
        acc[6] += f3.x * v; acc[7] += f3.y * v;
    }

    // merge the two half-warps (lane l and l^16 hold the same columns)
    #pragma unroll
    for (int j = 0; j < 8; j++)
        acc[j] += __shfl_xor_sync(0xffffffffu, acc[j], 16);

    // coalesced streaming store: full 512B row across the warp
    float4 o;
    if (hw == 0) { o.x = acc[0]; o.y = acc[1]; o.z = acc[2]; o.w = acc[3]; }
    else         { o.x = acc[4]; o.y = acc[5]; o.z = acc[6]; o.w = acc[7]; }
    __stcs((float4*)(out + (size_t)row * D + helem + hw * 4), o);

    // reset per-row counter and (one thread) the work-steal counters so the
    // next graph replay starts from clean state
    if (lane == 0) g_cnt[row] = 0;
    if (blockIdx.x == 0 && threadIdx.x == 0) {
        g_wA = 0; g_wB = 0; g_wC = 0;
    }
}

// ---------------------------------------------------------------------------
extern "C" void kernel_launch(void* const* d_in, const int* in_sizes, int n_in,
                              void* d_out, int out_size) {
    const float* inputs   = (const float*)d_in[0];   // [B, D]
    const float* old_act  = (const float*)d_in[1];   // [ND, D]
    const int*   fields   = (const int*)  d_in[2];   // [B]
    const int*   sub_rows = (const int*)  d_in[3];   // [ESUB]
    const int*   sub_cols = (const int*)  d_in[4];
    const float* sub_vals = (const float*)d_in[5];
    const int*   sup_rows = (const int*)  d_in[6];   // [ESUP]
    const int*   sup_cols = (const int*)  d_in[7];
    const float* sup_vals = (const float*)d_in[8];
    float* out = (float*)d_out;

    // Zero only the tail of out beyond the accumulated region (accumulate
    // fully overwrites out[0 .. B*D); prep writes out[B*D]).
    if (out_size > B * D + 1) {
        cudaMemsetAsync(out + (B * D + 1), 0,
                        (size_t)(out_size - B * D - 1) * sizeof(float));
    }

    // Fused gather+convert+fill with dynamic chunk-stealing (counters arrive
    // zeroed: zero-init statics on first call; accumulate re-zeros them).
    prep_kernel<<<PREP_GRID, PREP_THREADS>>>(inputs, old_act, fields,
                                             sub_rows, sub_cols, sub_vals,
                                             sup_rows, sup_cols, sup_vals,
                                             out, out_size);

    // Register-accumulated SpMM over fp16 sources.
    accumulate_kernel<<<B / 8, 256>>>(out);
}